// round 12
// baseline (speedup 1.0000x reference)
#include <cuda_runtime.h>
#include <cstdint>

// KNN: B=4, N=8192, D=16, K=16. Output float32 [B, N, K] neighbor indices.
// R11: split-j decomposition. 1024 scan blocks (2x warp residency vs R10),
// each covers half the candidate range for 64 rows -> partial sorted top-16
// into device scratch; merge kernel combines. Distance arithmetic bit-identical
// to R10 (rel_err 1.790007e-4).

#define BATCH 4
#define NPTS  8192
#define DIM   16
#define KSEL  16
#define HALF  (NPTS / 2)      // 4096 candidates per scan block
#define TJ    256
#define NTILES_H (HALF / TJ)  // 16
#define THREADS 64
#define NROWS (BATCH * NPTS)  // 32768
#define X_ELEMS (NROWS * DIM)

__device__ __align__(16) float g_norms[NROWS];
__device__ __align__(16) float g_pd[NROWS * 2 * KSEL];   // partial dists
__device__ __align__(16) int   g_pi[NROWS * 2 * KSEL];   // partial indices

__global__ void knn_norms(const float* __restrict__ x) {
    int p = blockIdx.x * blockDim.x + threadIdx.x;   // 0..32767
    const float4* v = (const float4*)(x + (size_t)p * DIM);
    float4 a = v[0], b = v[1], c = v[2], e = v[3];
    float s = __fmul_rn(a.x, a.x);
    s = __fadd_rn(s, __fmul_rn(a.y, a.y));
    s = __fadd_rn(s, __fmul_rn(a.z, a.z));
    s = __fadd_rn(s, __fmul_rn(a.w, a.w));
    s = __fadd_rn(s, __fmul_rn(b.x, b.x));
    s = __fadd_rn(s, __fmul_rn(b.y, b.y));
    s = __fadd_rn(s, __fmul_rn(b.z, b.z));
    s = __fadd_rn(s, __fmul_rn(b.w, b.w));
    s = __fadd_rn(s, __fmul_rn(c.x, c.x));
    s = __fadd_rn(s, __fmul_rn(c.y, c.y));
    s = __fadd_rn(s, __fmul_rn(c.z, c.z));
    s = __fadd_rn(s, __fmul_rn(c.w, c.w));
    s = __fadd_rn(s, __fmul_rn(e.x, e.x));
    s = __fadd_rn(s, __fmul_rn(e.y, e.y));
    s = __fadd_rn(s, __fmul_rn(e.z, e.z));
    s = __fadd_rn(s, __fmul_rn(e.w, e.w));
    g_norms[p] = s;
}

__global__ void __launch_bounds__(THREADS, 8)
knn_scan(const float* __restrict__ x) {
    __shared__ __align__(16) float s_pts[TJ * DIM];   // 16 KB
    __shared__ __align__(16) float s_nrm[TJ];         //  1 KB

    const int bid   = blockIdx.x;
    const int half  = bid & 1;                 // candidate half 0/1
    const int rb    = bid >> 1;                // row-block 0..511
    const int tid   = threadIdx.x;
    const int grow  = rb * THREADS + tid;      // global row 0..32767
    const int batch = grow >> 13;
    const int row   = grow & (NPTS - 1);

    const float* xb = x + (size_t)batch * NPTS * DIM;
    const float* nb = g_norms + batch * NPTS;

    // query into registers + own norm (precomputed, bit-identical)
    float q[DIM];
    {
        const float4* qv = (const float4*)(xb + (size_t)row * DIM);
        float4 a = qv[0], b = qv[1], c = qv[2], e = qv[3];
        q[0]=a.x; q[1]=a.y; q[2]=a.z; q[3]=a.w;
        q[4]=b.x; q[5]=b.y; q[6]=b.z; q[7]=b.w;
        q[8]=c.x; q[9]=c.y; q[10]=c.z; q[11]=c.w;
        q[12]=e.x; q[13]=e.y; q[14]=e.z; q[15]=e.w;
    }
    const float ni = nb[row];

    float d[KSEL];
    int   id[KSEL];
#pragma unroll
    for (int t = 0; t < KSEL; ++t) { d[t] = __int_as_float(0x7F800000); id[t] = 0; }

    const int jstart = half * HALF;

    for (int tile = 0; tile < NTILES_H; ++tile) {
        const int jbase = jstart + tile * TJ;

        // cooperative tile load: points + norms
        {
            const float4* src = (const float4*)(xb + (size_t)jbase * DIM);
            float4* dst = (float4*)s_pts;
#pragma unroll
            for (int v = 0; v < TJ * DIM / 4 / THREADS; ++v)
                dst[tid + v * THREADS] = src[tid + v * THREADS];
            ((float4*)s_nrm)[tid] = ((const float4*)(nb + jbase))[tid];
        }
        __syncthreads();

        // scan: broadcast LDS.128, quads consumed directly
#pragma unroll 4
        for (int jl = 0; jl < TJ; ++jl) {
            const float4* pv = (const float4*)(s_pts + jl * DIM);
            float4 a = pv[0], b = pv[1], c = pv[2], e = pv[3];
            float dot = __fmul_rn(q[0], a.x);
            dot = __fmaf_rn(q[1],  a.y, dot);
            dot = __fmaf_rn(q[2],  a.z, dot);
            dot = __fmaf_rn(q[3],  a.w, dot);
            dot = __fmaf_rn(q[4],  b.x, dot);
            dot = __fmaf_rn(q[5],  b.y, dot);
            dot = __fmaf_rn(q[6],  b.z, dot);
            dot = __fmaf_rn(q[7],  b.w, dot);
            dot = __fmaf_rn(q[8],  c.x, dot);
            dot = __fmaf_rn(q[9],  c.y, dot);
            dot = __fmaf_rn(q[10], c.z, dot);
            dot = __fmaf_rn(q[11], c.w, dot);
            dot = __fmaf_rn(q[12], e.x, dot);
            dot = __fmaf_rn(q[13], e.y, dot);
            dot = __fmaf_rn(q[14], e.z, dot);
            dot = __fmaf_rn(q[15], e.w, dot);
            float t1   = __fadd_rn(ni, __fmul_rn(-2.0f, dot));
            float dist = __fadd_rn(t1, s_nrm[jl]);

            if (dist < d[KSEL - 1]) {              // strict: ties keep earlier j
                d[KSEL - 1]  = dist;
                id[KSEL - 1] = jbase + jl;
#pragma unroll
                for (int t = KSEL - 1; t > 0; --t) {
                    if (d[t] < d[t - 1]) {
                        float tf = d[t - 1];  d[t - 1]  = d[t];  d[t]  = tf;
                        int   ti = id[t - 1]; id[t - 1] = id[t]; id[t] = ti;
                    }
                }
            }
        }
        __syncthreads();
    }

    // write sorted partial list
    float* pd = g_pd + ((size_t)grow * 2 + half) * KSEL;
    int*   pi = g_pi + ((size_t)grow * 2 + half) * KSEL;
#pragma unroll
    for (int t = 0; t < KSEL; ++t) { pd[t] = d[t]; pi[t] = id[t]; }
}

__global__ void knn_merge(float* __restrict__ out) {
    const int grow = blockIdx.x * blockDim.x + threadIdx.x;  // 0..32767
    const float* d0 = g_pd + (size_t)grow * 2 * KSEL;
    const float* d1 = d0 + KSEL;
    const int*   i0 = g_pi + (size_t)grow * 2 * KSEL;
    const int*   i1 = i0 + KSEL;
    float* op = out + (size_t)grow * KSEL;

    int a = 0, b = 0;
    // all half-0 indices < half-1 indices, so ties (d0==d1) must take list 0
    // -> exact (dist, idx) lexicographic merge.
#pragma unroll
    for (int t = 0; t < KSEL; ++t) {
        float da = __ldg(d0 + a);
        float db = __ldg(d1 + b);
        bool take0 = (da <= db);
        int idx = take0 ? __ldg(i0 + a) : __ldg(i1 + b);
        a += take0 ? 1 : 0;
        b += take0 ? 0 : 1;
        op[t] = (float)idx;
    }
}

extern "C" void kernel_launch(void* const* d_in, const int* in_sizes, int n_in,
                              void* d_out, int out_size) {
    const float* x = nullptr;
    for (int i = 0; i < n_in; ++i)
        if (in_sizes[i] == X_ELEMS) { x = (const float*)d_in[i]; break; }
    if (!x)
        for (int i = 0; i < n_in; ++i)
            if (in_sizes[i] == X_ELEMS * 4) { x = (const float*)d_in[i]; break; }
    if (!x) {
        int best = 0;
        for (int i = 1; i < n_in; ++i)
            if (in_sizes[i] > in_sizes[best]) best = i;
        x = (const float*)d_in[best];
    }
    knn_norms<<<NROWS / 256, 256>>>(x);
    knn_scan<<<(NROWS / THREADS) * 2, THREADS>>>(x);
    knn_merge<<<NROWS / 256, 256>>>((float*)d_out);
}

// round 13
// speedup vs baseline: 1.0048x; 1.0048x over previous
#include <cuda_runtime.h>
#include <cstdint>

// KNN: B=4, N=8192, D=16, K=16. Output float32 [B, N, K] neighbor indices.
// R11: split-j decomposition. 1024 scan blocks (2x warp residency vs R10),
// each covers half the candidate range for 64 rows -> partial sorted top-16
// into device scratch; merge kernel combines. Distance arithmetic bit-identical
// to R10 (rel_err 1.790007e-4).

#define BATCH 4
#define NPTS  8192
#define DIM   16
#define KSEL  16
#define HALF  (NPTS / 2)      // 4096 candidates per scan block
#define TJ    256
#define NTILES_H (HALF / TJ)  // 16
#define THREADS 64
#define NROWS (BATCH * NPTS)  // 32768
#define X_ELEMS (NROWS * DIM)

__device__ __align__(16) float g_norms[NROWS];
__device__ __align__(16) float g_pd[NROWS * 2 * KSEL];   // partial dists
__device__ __align__(16) int   g_pi[NROWS * 2 * KSEL];   // partial indices

__global__ void knn_norms(const float* __restrict__ x) {
    int p = blockIdx.x * blockDim.x + threadIdx.x;   // 0..32767
    const float4* v = (const float4*)(x + (size_t)p * DIM);
    float4 a = v[0], b = v[1], c = v[2], e = v[3];
    float s = __fmul_rn(a.x, a.x);
    s = __fadd_rn(s, __fmul_rn(a.y, a.y));
    s = __fadd_rn(s, __fmul_rn(a.z, a.z));
    s = __fadd_rn(s, __fmul_rn(a.w, a.w));
    s = __fadd_rn(s, __fmul_rn(b.x, b.x));
    s = __fadd_rn(s, __fmul_rn(b.y, b.y));
    s = __fadd_rn(s, __fmul_rn(b.z, b.z));
    s = __fadd_rn(s, __fmul_rn(b.w, b.w));
    s = __fadd_rn(s, __fmul_rn(c.x, c.x));
    s = __fadd_rn(s, __fmul_rn(c.y, c.y));
    s = __fadd_rn(s, __fmul_rn(c.z, c.z));
    s = __fadd_rn(s, __fmul_rn(c.w, c.w));
    s = __fadd_rn(s, __fmul_rn(e.x, e.x));
    s = __fadd_rn(s, __fmul_rn(e.y, e.y));
    s = __fadd_rn(s, __fmul_rn(e.z, e.z));
    s = __fadd_rn(s, __fmul_rn(e.w, e.w));
    g_norms[p] = s;
}

__global__ void __launch_bounds__(THREADS, 8)
knn_scan(const float* __restrict__ x) {
    __shared__ __align__(16) float s_pts[TJ * DIM];   // 16 KB
    __shared__ __align__(16) float s_nrm[TJ];         //  1 KB

    const int bid   = blockIdx.x;
    const int half  = bid & 1;                 // candidate half 0/1
    const int rb    = bid >> 1;                // row-block 0..511
    const int tid   = threadIdx.x;
    const int grow  = rb * THREADS + tid;      // global row 0..32767
    const int batch = grow >> 13;
    const int row   = grow & (NPTS - 1);

    const float* xb = x + (size_t)batch * NPTS * DIM;
    const float* nb = g_norms + batch * NPTS;

    // query into registers + own norm (precomputed, bit-identical)
    float q[DIM];
    {
        const float4* qv = (const float4*)(xb + (size_t)row * DIM);
        float4 a = qv[0], b = qv[1], c = qv[2], e = qv[3];
        q[0]=a.x; q[1]=a.y; q[2]=a.z; q[3]=a.w;
        q[4]=b.x; q[5]=b.y; q[6]=b.z; q[7]=b.w;
        q[8]=c.x; q[9]=c.y; q[10]=c.z; q[11]=c.w;
        q[12]=e.x; q[13]=e.y; q[14]=e.z; q[15]=e.w;
    }
    const float ni = nb[row];

    float d[KSEL];
    int   id[KSEL];
#pragma unroll
    for (int t = 0; t < KSEL; ++t) { d[t] = __int_as_float(0x7F800000); id[t] = 0; }

    const int jstart = half * HALF;

    for (int tile = 0; tile < NTILES_H; ++tile) {
        const int jbase = jstart + tile * TJ;

        // cooperative tile load: points + norms
        {
            const float4* src = (const float4*)(xb + (size_t)jbase * DIM);
            float4* dst = (float4*)s_pts;
#pragma unroll
            for (int v = 0; v < TJ * DIM / 4 / THREADS; ++v)
                dst[tid + v * THREADS] = src[tid + v * THREADS];
            ((float4*)s_nrm)[tid] = ((const float4*)(nb + jbase))[tid];
        }
        __syncthreads();

        // scan: broadcast LDS.128, quads consumed directly
#pragma unroll 4
        for (int jl = 0; jl < TJ; ++jl) {
            const float4* pv = (const float4*)(s_pts + jl * DIM);
            float4 a = pv[0], b = pv[1], c = pv[2], e = pv[3];
            float dot = __fmul_rn(q[0], a.x);
            dot = __fmaf_rn(q[1],  a.y, dot);
            dot = __fmaf_rn(q[2],  a.z, dot);
            dot = __fmaf_rn(q[3],  a.w, dot);
            dot = __fmaf_rn(q[4],  b.x, dot);
            dot = __fmaf_rn(q[5],  b.y, dot);
            dot = __fmaf_rn(q[6],  b.z, dot);
            dot = __fmaf_rn(q[7],  b.w, dot);
            dot = __fmaf_rn(q[8],  c.x, dot);
            dot = __fmaf_rn(q[9],  c.y, dot);
            dot = __fmaf_rn(q[10], c.z, dot);
            dot = __fmaf_rn(q[11], c.w, dot);
            dot = __fmaf_rn(q[12], e.x, dot);
            dot = __fmaf_rn(q[13], e.y, dot);
            dot = __fmaf_rn(q[14], e.z, dot);
            dot = __fmaf_rn(q[15], e.w, dot);
            float t1   = __fadd_rn(ni, __fmul_rn(-2.0f, dot));
            float dist = __fadd_rn(t1, s_nrm[jl]);

            if (dist < d[KSEL - 1]) {              // strict: ties keep earlier j
                d[KSEL - 1]  = dist;
                id[KSEL - 1] = jbase + jl;
#pragma unroll
                for (int t = KSEL - 1; t > 0; --t) {
                    if (d[t] < d[t - 1]) {
                        float tf = d[t - 1];  d[t - 1]  = d[t];  d[t]  = tf;
                        int   ti = id[t - 1]; id[t - 1] = id[t]; id[t] = ti;
                    }
                }
            }
        }
        __syncthreads();
    }

    // write sorted partial list
    float* pd = g_pd + ((size_t)grow * 2 + half) * KSEL;
    int*   pi = g_pi + ((size_t)grow * 2 + half) * KSEL;
#pragma unroll
    for (int t = 0; t < KSEL; ++t) { pd[t] = d[t]; pi[t] = id[t]; }
}

__global__ void knn_merge(float* __restrict__ out) {
    const int grow = blockIdx.x * blockDim.x + threadIdx.x;  // 0..32767
    const float* d0 = g_pd + (size_t)grow * 2 * KSEL;
    const float* d1 = d0 + KSEL;
    const int*   i0 = g_pi + (size_t)grow * 2 * KSEL;
    const int*   i1 = i0 + KSEL;
    float* op = out + (size_t)grow * KSEL;

    int a = 0, b = 0;
    // all half-0 indices < half-1 indices, so ties (d0==d1) must take list 0
    // -> exact (dist, idx) lexicographic merge.
#pragma unroll
    for (int t = 0; t < KSEL; ++t) {
        float da = __ldg(d0 + a);
        float db = __ldg(d1 + b);
        bool take0 = (da <= db);
        int idx = take0 ? __ldg(i0 + a) : __ldg(i1 + b);
        a += take0 ? 1 : 0;
        b += take0 ? 0 : 1;
        op[t] = (float)idx;
    }
}

extern "C" void kernel_launch(void* const* d_in, const int* in_sizes, int n_in,
                              void* d_out, int out_size) {
    const float* x = nullptr;
    for (int i = 0; i < n_in; ++i)
        if (in_sizes[i] == X_ELEMS) { x = (const float*)d_in[i]; break; }
    if (!x)
        for (int i = 0; i < n_in; ++i)
            if (in_sizes[i] == X_ELEMS * 4) { x = (const float*)d_in[i]; break; }
    if (!x) {
        int best = 0;
        for (int i = 1; i < n_in; ++i)
            if (in_sizes[i] > in_sizes[best]) best = i;
        x = (const float*)d_in[best];
    }
    knn_norms<<<NROWS / 256, 256>>>(x);
    knn_scan<<<(NROWS / THREADS) * 2, THREADS>>>(x);
    knn_merge<<<NROWS / 256, 256>>>((float*)d_out);
}